// round 1
// baseline (speedup 1.0000x reference)
#include <cuda_runtime.h>
#include <stdint.h>

#define N_NODES 100000
#define N_EDGES 2000000
#define PER 12
#define H 128
#define EPW 8                    // edges per warp tile
#define WARPS 8                  // warps per block (256 threads)
#define NTILES (N_EDGES / EPW)   // 250000 exact
#define EDGE_BLOCKS 296          // 2 blocks/SM on 148 SMs

// Scratch (allocation-free rule: __device__ globals)
__device__ float g_P[N_NODES * H];   // node_embs @ W1[:12] + b1
__device__ float g_Q[N_NODES * H];   // node_embs @ W1[12:]
__device__ double g_sum;             // sum over edges of h2 . Wa

// ---------------------------------------------------------------------------
// Kernel A: per-node precompute of P and Q. One warp per node, lane owns 4 cols.
// ---------------------------------------------------------------------------
__global__ void precompute_kernel(const float* __restrict__ E,
                                  const float* __restrict__ W1,
                                  const float* __restrict__ b1) {
    if (blockIdx.x == 0 && threadIdx.x == 0) g_sum = 0.0;
    int warp = (blockIdx.x * blockDim.x + threadIdx.x) >> 5;
    int lane = threadIdx.x & 31;
    if (warp >= N_NODES) return;

    const float* e = E + warp * PER;
    float ek[PER];
#pragma unroll
    for (int k = 0; k < PER; ++k) ek[k] = __ldg(e + k);

    int j = lane << 2;
    float4 p = *(const float4*)(b1 + j);
    float4 q = make_float4(0.f, 0.f, 0.f, 0.f);
#pragma unroll
    for (int k = 0; k < PER; ++k) {
        float4 wa = *(const float4*)(W1 + k * H + j);
        float4 wb = *(const float4*)(W1 + (k + PER) * H + j);
        p.x += ek[k] * wa.x; p.y += ek[k] * wa.y;
        p.z += ek[k] * wa.z; p.w += ek[k] * wa.w;
        q.x += ek[k] * wb.x; q.y += ek[k] * wb.y;
        q.z += ek[k] * wb.z; q.w += ek[k] * wb.w;
    }
    *(float4*)(g_P + warp * H + j) = p;
    *(float4*)(g_Q + warp * H + j) = q;
}

// ---------------------------------------------------------------------------
// Kernel B: per-edge h1 = relu(P[src]+Q[dst]); h2 = relu(h1 @ W2 + b2);
//           out[e] = h2.(Wv+Wa) + bv;  g_sum += h2.Wa
// Warp-register-tiled GEMM with packed fma.rn.f32x2.
// ---------------------------------------------------------------------------
extern __shared__ float ws[];   // W2 staged: 128x128 f32 = 64 KB

__global__ void __launch_bounds__(256, 2)
edge_kernel(const int* __restrict__ src, const int* __restrict__ dst,
            const float* __restrict__ W2, const float* __restrict__ b2,
            const float* __restrict__ Wv, const float* __restrict__ bv,
            const float* __restrict__ Wa, float* __restrict__ out) {
    int tid = threadIdx.x;
    // Stage W2 (row-major [k][j]) into smem once per block
    for (int i = tid; i < H * H / 4; i += 256)
        *(float4*)(ws + i * 4) = *(const float4*)(W2 + i * 4);
    __syncthreads();

    int lane = tid & 31;
    int wid  = tid >> 5;
    int j = lane << 2;

    float4 b2v = *(const float4*)(b2 + j);
    float4 wav = *(const float4*)(Wa + j);
    float4 wvv = *(const float4*)(Wv + j);
    float4 wcv = make_float4(wav.x + wvv.x, wav.y + wvv.y,
                             wav.z + wvv.z, wav.w + wvv.w);
    float bv0 = __ldg(bv);

    uint64_t bc01, bc23;
    asm("mov.b64 %0, {%1, %2};" : "=l"(bc01) : "f"(b2v.x), "f"(b2v.y));
    asm("mov.b64 %0, {%1, %2};" : "=l"(bc23) : "f"(b2v.z), "f"(b2v.w));

    float asum = 0.f;
    const ulonglong2* wsp = (const ulonglong2*)ws;   // 16B units: index k*32+lane

    int gw = blockIdx.x * WARPS + wid;
    int nw = gridDim.x * WARPS;

    for (int t = gw; t < NTILES; t += nw) {
        int base = t * EPW;
        float h[EPW][4];
        uint64_t a0[EPW], a1[EPW];
#pragma unroll
        for (int e = 0; e < EPW; ++e) {
            int s = __ldg(src + base + e);
            int d = __ldg(dst + base + e);
            float4 p = *(const float4*)(g_P + s * H + j);
            float4 q = *(const float4*)(g_Q + d * H + j);
            h[e][0] = fmaxf(p.x + q.x, 0.f);
            h[e][1] = fmaxf(p.y + q.y, 0.f);
            h[e][2] = fmaxf(p.z + q.z, 0.f);
            h[e][3] = fmaxf(p.w + q.w, 0.f);
            a0[e] = bc01; a1[e] = bc23;
        }

        // h2[j..j+3] accumulation: k = kk*4 + c, h1[k] lives in lane kk comp c
#pragma unroll 2
        for (int kk = 0; kk < 32; ++kk) {
#pragma unroll
            for (int c = 0; c < 4; ++c) {
                ulonglong2 w = wsp[((kk << 2) + c) * 32 + lane];
#pragma unroll
                for (int e = 0; e < EPW; ++e) {
                    float a = __shfl_sync(0xffffffffu, h[e][c], kk);
                    uint64_t ad;
                    asm("mov.b64 %0, {%1, %1};" : "=l"(ad) : "f"(a));
                    asm("fma.rn.f32x2 %0, %1, %2, %0;"
                        : "+l"(a0[e]) : "l"(ad), "l"(w.x));
                    asm("fma.rn.f32x2 %0, %1, %2, %0;"
                        : "+l"(a1[e]) : "l"(ad), "l"(w.y));
                }
            }
        }

        // Epilogue: relu + two dots + warp reduction
#pragma unroll
        for (int e = 0; e < EPW; ++e) {
            float h0, h1v, h2v, h3;
            asm("mov.b64 {%0, %1}, %2;" : "=f"(h0),  "=f"(h1v) : "l"(a0[e]));
            asm("mov.b64 {%0, %1}, %2;" : "=f"(h2v), "=f"(h3)  : "l"(a1[e]));
            h0  = fmaxf(h0,  0.f); h1v = fmaxf(h1v, 0.f);
            h2v = fmaxf(h2v, 0.f); h3  = fmaxf(h3,  0.f);
            float qp = h0 * wcv.x + h1v * wcv.y + h2v * wcv.z + h3 * wcv.w;
            float av = h0 * wav.x + h1v * wav.y + h2v * wav.z + h3 * wav.w;
#pragma unroll
            for (int off = 16; off; off >>= 1) {
                qp += __shfl_xor_sync(0xffffffffu, qp, off);
                av += __shfl_xor_sync(0xffffffffu, av, off);
            }
            if (lane == 0) {
                out[base + e] = qp + bv0;
                asum += av;
            }
        }
    }

    // Block-level reduction of adv sum, one double atomic per block
    __shared__ float red[WARPS];
#pragma unroll
    for (int off = 16; off; off >>= 1)
        asum += __shfl_xor_sync(0xffffffffu, asum, off);
    if (lane == 0) red[wid] = asum;
    __syncthreads();
    if (tid == 0) {
        float s = 0.f;
#pragma unroll
        for (int i = 0; i < WARPS; ++i) s += red[i];
        atomicAdd(&g_sum, (double)s);
    }
}

// ---------------------------------------------------------------------------
// Kernel C: subtract mean(adv) in place
// ---------------------------------------------------------------------------
__global__ void finalize_kernel(float* __restrict__ out) {
    int i = blockIdx.x * blockDim.x + threadIdx.x;
    if (i < N_EDGES) {
        float mean = (float)(g_sum * (1.0 / (double)N_EDGES));
        out[i] -= mean;
    }
}

// ---------------------------------------------------------------------------
extern "C" void kernel_launch(void* const* d_in, const int* in_sizes, int n_in,
                              void* d_out, int out_size) {
    const float* node_embs = (const float*)d_in[0];
    const int*   src       = (const int*)d_in[1];
    const int*   dst       = (const int*)d_in[2];
    const float* W1        = (const float*)d_in[3];
    const float* b1        = (const float*)d_in[4];
    const float* W2        = (const float*)d_in[5];
    const float* b2        = (const float*)d_in[6];
    const float* Wv        = (const float*)d_in[7];
    const float* bv        = (const float*)d_in[8];
    const float* Wa        = (const float*)d_in[9];
    // ba (d_in[10]) cancels algebraically in q
    float* out = (float*)d_out;

    precompute_kernel<<<(N_NODES * 32 + 255) / 256, 256>>>(node_embs, W1, b1);

    cudaFuncSetAttribute(edge_kernel,
                         cudaFuncAttributeMaxDynamicSharedMemorySize, 65536);
    edge_kernel<<<EDGE_BLOCKS, 256, 65536>>>(src, dst, W2, b2, Wv, bv, Wa, out);

    finalize_kernel<<<(N_EDGES + 255) / 256, 256>>>(out);
}

// round 3
// speedup vs baseline: 1.9530x; 1.9530x over previous
#include <cuda_runtime.h>
#include <cuda_bf16.h>
#include <stdint.h>

#define N_NODES 100000
#define N_EDGES 2000000
#define PER 12
#define H 128
#define TILE_M 128
#define NT (N_EDGES / TILE_M)   // 15625
#define GRID 148

// ---------------- device scratch (allocation-free rule) ----------------
__device__ float g_P[N_NODES * H];          // node_embs @ W1[:12] + b1
__device__ float g_Q[N_NODES * H];          // node_embs @ W1[12:]
__device__ unsigned char g_Bth[H * H * 2];  // W2^T bf16 hi, swizzled [n][k]
__device__ unsigned char g_Btl[H * H * 2];  // W2^T bf16 lo
__device__ double g_sum;

// ---------------- helpers ----------------
__device__ __forceinline__ uint32_t smem_to_u32(const void* p) {
    uint32_t a;
    asm("{ .reg .u64 t; cvta.to.shared.u64 t, %1; cvt.u32.u64 %0, t; }" : "=r"(a) : "l"(p));
    return a;
}
#define MBARRIER_INIT(addr, cnt) \
    asm volatile("mbarrier.init.shared.b64 [%0], %1;" :: "r"((uint32_t)(addr)), "r"((uint32_t)(cnt)) : "memory")
#define MBARRIER_ARRIVE(addr) \
    asm volatile("mbarrier.arrive.shared.b64 _, [%0];" :: "r"((uint32_t)(addr)) : "memory")
#define MBARRIER_WAIT_PARITY(addr, par) do { \
    uint32_t _m = (uint32_t)(addr), _p = (uint32_t)(par), _d; \
    asm volatile("{\n\t.reg .pred p;\n\tmbarrier.try_wait.parity.acquire.cta.shared::cta.b64 p, [%1], %2;\n\tselp.b32 %0, 1, 0, p;\n\t}" \
        : "=r"(_d) : "r"(_m), "r"(_p) : "memory"); \
    if (!_d) { \
        asm volatile("{\n\t.reg .pred P1;\n\tWL_%=:\n\tmbarrier.try_wait.parity.acquire.cta.shared::cta.b64 P1, [%0], %1, 0x989680;\n\t@P1 bra.uni WD_%=;\n\tbra.uni WL_%=;\n\tWD_%=:\n\t}" \
            :: "r"(_m), "r"(_p) : "memory"); \
    } } while (0)
#define NAMED_BAR(id, n) asm volatile("bar.sync %0, %1;" :: "r"(id), "r"(n) : "memory")
// pack: lo16 = bf16(x), hi16 = bf16(y)
#define PACK_BF2(d, x, y) \
    asm("cvt.rn.bf16x2.f32 %0, %1, %2;" : "=r"(d) : "f"(y), "f"(x))
#define LDSM_X4(r0, r1, r2, r3, addr) \
    asm volatile("ldmatrix.sync.aligned.m8n8.x4.shared.b16 {%0,%1,%2,%3}, [%4];" \
        : "=r"(r0), "=r"(r1), "=r"(r2), "=r"(r3) : "r"(addr))
#define MMA16816(d, a0, a1, a2, a3, b0, b1) \
    asm volatile("mma.sync.aligned.m16n8k16.row.col.f32.bf16.bf16.f32 " \
        "{%0,%1,%2,%3}, {%4,%5,%6,%7}, {%8,%9}, {%0,%1,%2,%3};" \
        : "+f"((d)[0]), "+f"((d)[1]), "+f"((d)[2]), "+f"((d)[3]) \
        : "r"(a0), "r"(a1), "r"(a2), "r"(a3), "r"(b0), "r"(b1))

// ---------------- SMEM layout ----------------
#define SO_MBAR 0        // full0,full1,free0,free1 (8B each)
#define SO_EP   1024     // 128 x float4 {b2, Wv+Wa, Wa, 0}
#define SO_PART 3072     // 128 rows x 4 warps x float2 = 4KB
#define SO_B    8192     // Bt hi 32KB, lo 32KB
#define SO_A    73728    // + s*65536 : hi 32KB, lo +32768
#define SMEM_TOTAL 204800

// ---------------------------------------------------------------------------
// Kernel A: P = E@W1_top + b1 ; Q = E@W1_bot. One warp per node.
// ---------------------------------------------------------------------------
__global__ void precompute_kernel(const float* __restrict__ E,
                                  const float* __restrict__ W1,
                                  const float* __restrict__ b1) {
    if (blockIdx.x == 0 && threadIdx.x == 0) g_sum = 0.0;
    int warp = (blockIdx.x * blockDim.x + threadIdx.x) >> 5;
    int lane = threadIdx.x & 31;
    if (warp >= N_NODES) return;
    const float* e = E + warp * PER;
    float ek[PER];
#pragma unroll
    for (int k = 0; k < PER; ++k) ek[k] = __ldg(e + k);
    int j = lane << 2;
    float4 p = *(const float4*)(b1 + j);
    float4 q = make_float4(0.f, 0.f, 0.f, 0.f);
#pragma unroll
    for (int k = 0; k < PER; ++k) {
        float4 wa = *(const float4*)(W1 + k * H + j);
        float4 wb = *(const float4*)(W1 + (k + PER) * H + j);
        p.x += ek[k] * wa.x; p.y += ek[k] * wa.y; p.z += ek[k] * wa.z; p.w += ek[k] * wa.w;
        q.x += ek[k] * wb.x; q.y += ek[k] * wb.y; q.z += ek[k] * wb.z; q.w += ek[k] * wb.w;
    }
    *(float4*)(g_P + warp * H + j) = p;
    *(float4*)(g_Q + warp * H + j) = q;
}

// ---------------------------------------------------------------------------
// Kernel A2: W2^T -> bf16 hi/lo, swizzled [n][k]: byte = n*256 +
//            (((k>>3) ^ (n&7))<<4) + (k&7)*2
// ---------------------------------------------------------------------------
__global__ void prep_w2_kernel(const float* __restrict__ W2) {
    int i = blockIdx.x * blockDim.x + threadIdx.x;
    if (i >= H * H) return;
    int n = i >> 7, k = i & 127;
    float x = W2[k * H + n];
    __nv_bfloat16 hb16 = __float2bfloat16(x);
    unsigned short hb = *(unsigned short*)&hb16;
    float hf = __uint_as_float((uint32_t)hb << 16);
    __nv_bfloat16 lb16 = __float2bfloat16(x - hf);
    unsigned short lb = *(unsigned short*)&lb16;
    uint32_t off = ((uint32_t)n << 8) + ((((uint32_t)(k >> 3)) ^ (uint32_t)(n & 7)) << 4)
                 + (((uint32_t)k & 7u) << 1);
    *(unsigned short*)(g_Bth + off) = hb;
    *(unsigned short*)(g_Btl + off) = lb;
}

// ---------------------------------------------------------------------------
// Kernel B: warp-specialized HMMA pipeline.
//   warps 4-7 (producers): gather h1 = relu(P[src]+Q[dst]), bf16 hi/lo split
//                          into double-buffered swizzled SMEM A.
//   warps 0-3 (consumers): each owns n-slice of 32; 768 mma.m16n8k16 per tile;
//                          in-register dueling-head epilogue.
// ---------------------------------------------------------------------------
extern __shared__ unsigned char smx[];

__global__ void __launch_bounds__(256, 1)
edge_kernel(const int* __restrict__ src, const int* __restrict__ dst,
            const float* __restrict__ b2, const float* __restrict__ Wv,
            const float* __restrict__ bv, const float* __restrict__ Wa,
            float* __restrict__ out) {
    uint32_t sb = smem_to_u32(smx);
    int tid = threadIdx.x, wid = tid >> 5, lane = tid & 31;

    if (tid == 0) {
        MBARRIER_INIT(sb + SO_MBAR + 0, 128);   // full[0] (producer arrivals)
        MBARRIER_INIT(sb + SO_MBAR + 8, 128);   // full[1]
        MBARRIER_INIT(sb + SO_MBAR + 16, 128);  // free[0] (consumer arrivals)
        MBARRIER_INIT(sb + SO_MBAR + 24, 128);  // free[1]
    }
    if (tid < H) {
        float wa = Wa[tid];
        ((float4*)(smx + SO_EP))[tid] = make_float4(b2[tid], Wv[tid] + wa, wa, 0.f);
    }
    {   // stage pre-swizzled W2^T hi/lo into SMEM
        const int4* s1 = (const int4*)g_Bth;
        const int4* s2 = (const int4*)g_Btl;
        int4* d1 = (int4*)(smx + SO_B);
        int4* d2 = (int4*)(smx + SO_B + 32768);
        for (int i = tid; i < 2048; i += 256) { d1[i] = s1[i]; d2[i] = s2[i]; }
    }
    __syncthreads();
    float bv0 = __ldg(bv);
    float asum = 0.f;

    if (wid >= 4) {
        // ======================= PRODUCERS =======================
        int r = tid - 128;                 // row 0..127
        uint32_t xr = (uint32_t)(r & 7);
        int s = 0, ph = 1;
        for (int t = blockIdx.x; t < NT; t += GRID) {
            MBARRIER_WAIT_PARITY(sb + SO_MBAR + 16 + s * 8, ph);   // buf free
            int si = __ldg(src + t * TILE_M + r);
            int di = __ldg(dst + t * TILE_M + r);
            const float4* Pp = (const float4*)(g_P + si * H);
            const float4* Qp = (const float4*)(g_Q + di * H);
            uint32_t ahb = sb + SO_A + (uint32_t)s * 65536u + ((uint32_t)r << 8);
#pragma unroll 4
            for (int c = 0; c < 16; ++c) {   // 8 cols per chunk
                float4 pa = Pp[2 * c], pb = Pp[2 * c + 1];
                float4 qa = Qp[2 * c], qb = Qp[2 * c + 1];
                float v0 = fmaxf(pa.x + qa.x, 0.f), v1 = fmaxf(pa.y + qa.y, 0.f);
                float v2 = fmaxf(pa.z + qa.z, 0.f), v3 = fmaxf(pa.w + qa.w, 0.f);
                float v4 = fmaxf(pb.x + qb.x, 0.f), v5 = fmaxf(pb.y + qb.y, 0.f);
                float v6 = fmaxf(pb.z + qb.z, 0.f), v7 = fmaxf(pb.w + qb.w, 0.f);
                uint32_t h0, h1, h2, h3, l0, l1, l2, l3;
                PACK_BF2(h0, v0, v1); PACK_BF2(h1, v2, v3);
                PACK_BF2(h2, v4, v5); PACK_BF2(h3, v6, v7);
                float r0 = v0 - __uint_as_float(h0 << 16);
                float r1 = v1 - __uint_as_float(h0 & 0xffff0000u);
                float r2 = v2 - __uint_as_float(h1 << 16);
                float r3 = v3 - __uint_as_float(h1 & 0xffff0000u);
                float r4 = v4 - __uint_as_float(h2 << 16);
                float r5 = v5 - __uint_as_float(h2 & 0xffff0000u);
                float r6 = v6 - __uint_as_float(h3 << 16);
                float r7 = v7 - __uint_as_float(h3 & 0xffff0000u);
                PACK_BF2(l0, r0, r1); PACK_BF2(l1, r2, r3);
                PACK_BF2(l2, r4, r5); PACK_BF2(l3, r6, r7);
                uint32_t off = (((uint32_t)c ^ xr) << 4);
                asm volatile("st.shared.v4.b32 [%0], {%1,%2,%3,%4};"
                             :: "r"(ahb + off), "r"(h0), "r"(h1), "r"(h2), "r"(h3) : "memory");
                asm volatile("st.shared.v4.b32 [%0], {%1,%2,%3,%4};"
                             :: "r"(ahb + off + 32768u), "r"(l0), "r"(l1), "r"(l2), "r"(l3) : "memory");
            }
            MBARRIER_ARRIVE(sb + SO_MBAR + s * 8);   // buf full
            s ^= 1; if (!s) ph ^= 1;
        }
    } else {
        // ======================= CONSUMERS =======================
        int w = wid;                 // n-slice [32w, 32w+32)
        int g = lane >> 3, lr = lane & 7;
        uint32_t xr = (uint32_t)lr;
        // A lane geometry: row_local = (g&1)*8 + lr, chunk bit = g>>1
        uint32_t a_rowoff = ((uint32_t)(((g & 1) << 3) + lr)) << 8;
        uint32_t a_cs = (uint32_t)(g >> 1);
        // B lane geometry: row = 32w + (g>>1)*8 + lr, chunk bit = g&1
        uint32_t b_row0 = (uint32_t)(32 * w + ((g >> 1) << 3) + lr);
        uint32_t b_cs = (uint32_t)(g & 1);
        uint32_t Bbase = sb + SO_B;
        const float4* ep = (const float4*)(smx + SO_EP);
        float2* part = (float2*)(smx + SO_PART);
        int c0base = 32 * w + 2 * (lane & 3);

        int s = 0, ph = 0;
        for (int t = blockIdx.x; t < NT; t += GRID) {
            MBARRIER_WAIT_PARITY(sb + SO_MBAR + s * 8, ph);   // buf full
            uint32_t Ah = sb + SO_A + (uint32_t)s * 65536u + a_rowoff;
            float acc[8][16];
#pragma unroll
            for (int i = 0; i < 8; ++i)
#pragma unroll
                for (int j = 0; j < 16; ++j) acc[i][j] = 0.f;
#pragma unroll
            for (int ks = 0; ks < 8; ++ks) {
                uint32_t bch = (((uint32_t)(2 * ks) + b_cs) ^ xr) << 4;
                uint32_t ba0 = Bbase + (b_row0 << 8) + bch;
                uint32_t ba1 = ba0 + (16u << 8);
                uint32_t bh0, bh1, bh2, bh3, bh4, bh5, bh6, bh7;
                uint32_t bl0, bl1, bl2, bl3, bl4, bl5, bl6, bl7;
                LDSM_X4(bh0, bh1, bh2, bh3, ba0);
                LDSM_X4(bh4, bh5, bh6, bh7, ba1);
                LDSM_X4(bl0, bl1, bl2, bl3, ba0 + 32768u);
                LDSM_X4(bl4, bl5, bl6, bl7, ba1 + 32768u);
                uint32_t ach = (((uint32_t)(2 * ks) + a_cs) ^ xr) << 4;
#pragma unroll
                for (int mb = 0; mb < 8; ++mb) {
                    uint32_t aa = Ah + ((uint32_t)mb << 12) + ach;
                    uint32_t a0, a1, a2, a3, c0, c1, c2, c3;
                    LDSM_X4(a0, a1, a2, a3, aa);
                    LDSM_X4(c0, c1, c2, c3, aa + 32768u);
                    MMA16816(acc[mb] + 0,  a0, a1, a2, a3, bh0, bh1);
                    MMA16816(acc[mb] + 0,  a0, a1, a2, a3, bl0, bl1);
                    MMA16816(acc[mb] + 0,  c0, c1, c2, c3, bh0, bh1);
                    MMA16816(acc[mb] + 4,  a0, a1, a2, a3, bh2, bh3);
                    MMA16816(acc[mb] + 4,  a0, a1, a2, a3, bl2, bl3);
                    MMA16816(acc[mb] + 4,  c0, c1, c2, c3, bh2, bh3);
                    MMA16816(acc[mb] + 8,  a0, a1, a2, a3, bh4, bh5);
                    MMA16816(acc[mb] + 8,  a0, a1, a2, a3, bl4, bl5);
                    MMA16816(acc[mb] + 8,  c0, c1, c2, c3, bh4, bh5);
                    MMA16816(acc[mb] + 12, a0, a1, a2, a3, bh6, bh7);
                    MMA16816(acc[mb] + 12, a0, a1, a2, a3, bl6, bl7);
                    MMA16816(acc[mb] + 12, c0, c1, c2, c3, bh6, bh7);
                }
            }
            MBARRIER_ARRIVE(sb + SO_MBAR + 16 + s * 8);   // buf free

            // ---- epilogue: relu + dueling heads, all in registers ----
            float4 e0[4], e1[4];
#pragma unroll
            for (int f = 0; f < 4; ++f) {
                e0[f] = ep[c0base + 8 * f];
                e1[f] = ep[c0base + 8 * f + 1];
            }
#pragma unroll
            for (int mb = 0; mb < 8; ++mb) {
                float qp0 = 0.f, av0 = 0.f, qp1 = 0.f, av1 = 0.f;
#pragma unroll
                for (int f = 0; f < 4; ++f) {
                    float h;
                    h = fmaxf(acc[mb][4 * f + 0] + e0[f].x, 0.f); qp0 += h * e0[f].y; av0 += h * e0[f].z;
                    h = fmaxf(acc[mb][4 * f + 1] + e1[f].x, 0.f); qp0 += h * e1[f].y; av0 += h * e1[f].z;
                    h = fmaxf(acc[mb][4 * f + 2] + e0[f].x, 0.f); qp1 += h * e0[f].y; av1 += h * e0[f].z;
                    h = fmaxf(acc[mb][4 * f + 3] + e1[f].x, 0.f); qp1 += h * e1[f].y; av1 += h * e1[f].z;
                }
                qp0 += __shfl_xor_sync(0xffffffffu, qp0, 1); qp0 += __shfl_xor_sync(0xffffffffu, qp0, 2);
                av0 += __shfl_xor_sync(0xffffffffu, av0, 1); av0 += __shfl_xor_sync(0xffffffffu, av0, 2);
                qp1 += __shfl_xor_sync(0xffffffffu, qp1, 1); qp1 += __shfl_xor_sync(0xffffffffu, qp1, 2);
                av1 += __shfl_xor_sync(0xffffffffu, av1, 1); av1 += __shfl_xor_sync(0xffffffffu, av1, 2);
                if ((lane & 3) == 0) {
                    int r0 = 16 * mb + (lane >> 2);
                    part[r0 * 4 + w] = make_float2(qp0, av0);
                    part[(r0 + 8) * 4 + w] = make_float2(qp1, av1);
                }
            }
            NAMED_BAR(1, 128);
            {
                int row = tid;   // consumers are exactly tid 0..127
                float4 u = ((const float4*)(smx + SO_PART))[row * 2];
                float4 v = ((const float4*)(smx + SO_PART))[row * 2 + 1];
                out[t * TILE_M + row] = u.x + u.z + v.x + v.z + bv0;
                asum += u.y + u.w + v.y + v.w;
            }
            NAMED_BAR(1, 128);
            s ^= 1; if (!s) ph ^= 1;
        }
    }

    __syncthreads();
    if (wid < 4) {
#pragma unroll
        for (int o = 16; o; o >>= 1) asum += __shfl_xor_sync(0xffffffffu, asum, o);
        if (lane == 0) ((float*)(smx + SO_PART))[wid] = asum;
    }
    __syncthreads();
    if (tid == 0) {
        const float* red = (const float*)(smx + SO_PART);
        atomicAdd(&g_sum, (double)(red[0] + red[1] + red[2] + red[3]));
    }
}

// ---------------------------------------------------------------------------
__global__ void finalize_kernel(float* __restrict__ out) {
    int i = blockIdx.x * blockDim.x + threadIdx.x;
    if (i < N_EDGES) {
        float mean = (float)(g_sum * (1.0 / (double)N_EDGES));
        out[i] -= mean;
    }
}

// ---------------------------------------------------------------------------
extern "C" void kernel_launch(void* const* d_in, const int* in_sizes, int n_in,
                              void* d_out, int out_size) {
    const float* node_embs = (const float*)d_in[0];
    const int*   src       = (const int*)d_in[1];
    const int*   dst       = (const int*)d_in[2];
    const float* W1        = (const float*)d_in[3];
    const float* b1        = (const float*)d_in[4];
    const float* W2        = (const float*)d_in[5];
    const float* b2        = (const float*)d_in[6];
    const float* Wv        = (const float*)d_in[7];
    const float* bv        = (const float*)d_in[8];
    const float* Wa        = (const float*)d_in[9];
    // ba (d_in[10]) cancels algebraically
    float* out = (float*)d_out;

    precompute_kernel<<<(N_NODES * 32 + 255) / 256, 256>>>(node_embs, W1, b1);
    prep_w2_kernel<<<(H * H + 255) / 256, 256>>>(W2);

    cudaFuncSetAttribute(edge_kernel,
                         cudaFuncAttributeMaxDynamicSharedMemorySize, SMEM_TOTAL);
    edge_kernel<<<GRID, 256, SMEM_TOTAL>>>(src, dst, b2, Wv, bv, Wa, out);

    finalize_kernel<<<(N_EDGES + 255) / 256, 256>>>(out);
}